// round 17
// baseline (speedup 1.0000x reference)
#include <cuda_runtime.h>

// Fixed problem dims
#define NB 4
#define NQv 512
#define MMv 512
#define DDv 256
#define HHv 256

// Scratch (device globals: no allocations allowed)
__device__ float    g_q[NB * NQv * HHv];     // projected q, [b*NQ+n][h]
__device__ unsigned g_kTh[NB * HHv * MMv];   // projected k, transposed, packed half2(k,k)
__device__ float    g_sc[NB * NQv * MMv];    // raw scores [b][n][m]

__device__ __forceinline__ float fex2(float x) {
    float y; asm("ex2.approx.f32 %0, %1;" : "=f"(y) : "f"(x)); return y;
}
__device__ __forceinline__ unsigned long long pk2(float a, float b) {
    unsigned long long r; asm("mov.b64 %0, {%1, %2};" : "=l"(r) : "f"(a), "f"(b)); return r;
}
__device__ __forceinline__ void fma2(unsigned long long &d, unsigned long long a, unsigned long long b) {
    asm("fma.rn.f32x2 %0, %1, %2, %0;" : "+l"(d) : "l"(a), "l"(b));
}
__device__ __forceinline__ float2 up2(unsigned long long v) {
    float2 r; asm("mov.b64 {%0, %1}, %2;" : "=f"(r.x), "=f"(r.y) : "l"(v)); return r;
}
__device__ __forceinline__ unsigned packh2(float lo, float hi) {
    unsigned r; asm("cvt.rn.f16x2.f32 %0, %1, %2;" : "=r"(r) : "f"(hi), "f"(lo)); return r;
}
__device__ __forceinline__ unsigned hadd2(unsigned a, unsigned b) {
    unsigned r; asm("add.f16x2 %0, %1, %2;" : "=r"(r) : "r"(a), "r"(b)); return r;
}
__device__ __forceinline__ unsigned htanh2(unsigned a) {
    unsigned r; asm("tanh.approx.f16x2 %0, %1;" : "=r"(r) : "r"(a)); return r;
}
__device__ __forceinline__ unsigned hfma2(unsigned a, unsigned b, unsigned c) {
    unsigned r; asm("fma.rn.f16x2 %0, %1, %2, %3;" : "=r"(r) : "r"(a), "r"(b), "r"(c)); return r;
}
__device__ __forceinline__ void drain2(unsigned p, float &f0, float &f1) {
    unsigned short lo, hi; float a, b;
    asm("mov.b32 {%0, %1}, %2;" : "=h"(lo), "=h"(hi) : "r"(p));
    asm("cvt.f32.f16 %0, %1;" : "=f"(a) : "h"(lo));
    asm("cvt.f32.f16 %0, %1;" : "=f"(b) : "h"(hi));
    f0 += a; f1 += b;
}
__device__ __forceinline__ float tf32r(float x) {
    unsigned u; asm("cvt.rna.tf32.f32 %0, %1;" : "=r"(u) : "f"(x));
    return __uint_as_float(u);
}
__device__ __forceinline__ void mma_tf32(float* c,
                                         unsigned a0, unsigned a1, unsigned a2, unsigned a3,
                                         unsigned b0, unsigned b1) {
    asm("mma.sync.aligned.m16n8k8.row.col.f32.tf32.tf32.f32 "
        "{%0,%1,%2,%3}, {%4,%5,%6,%7}, {%8,%9}, {%0,%1,%2,%3};"
        : "+f"(c[0]), "+f"(c[1]), "+f"(c[2]), "+f"(c[3])
        : "r"(a0), "r"(a1), "r"(a2), "r"(a3), "r"(b0), "r"(b1));
}

// ---------------------------------------------------------------------------
// Projection GEMM via split-tf32 tensor MMA, software-pipelined, with
// PERMUTED smem layout: staging writes values directly in fragment order, so
// the consumer loads a whole m16n8k8 A-frag with one LDS.128 and a B-frag
// with one LDS.64 (16 vector LDS/chunk vs 48 scalar before).
// Layouts:
//   AP[wm][mf][kkg][lane*4+slot], lane=((r&7)<<2)|(c&3),
//       slot=((r>>3)&1)+2*((c>>2)&1)  (r,c within 64x16 chunk)
//   BP[wn][nf][kkg][lane*2+slot], lane=((c&7)<<2)|(k&3), slot=(k>>2)&1
// 256 blocks (128 q, 128 kT), 256 thr = 8 warps (2m x 4n), tile 64x64.
// ---------------------------------------------------------------------------
__global__ __launch_bounds__(256) void proj_kernel(const float* __restrict__ query,
                                                   const float* __restrict__ key,
                                                   const float* __restrict__ Wq,
                                                   const float* __restrict__ Wk)
{
    __shared__ __align__(16) float APh[2][2][2][128];   // 4KB
    __shared__ __align__(16) float APl[2][2][2][128];   // 4KB
    __shared__ __align__(16) float BPh[4][2][2][64];    // 4KB
    __shared__ __align__(16) float BPl[4][2][2][64];    // 4KB

    int bid = blockIdx.x;
    int is_k = bid >> 7;
    int local = bid & 127;
    int row0 = (local >> 2) * 64;
    int col0 = (local & 3) * 64;
    const float* A = is_k ? key : query;
    const float* B = is_k ? Wk : Wq;

    int t = threadIdx.x;
    int lane = t & 31, wid = t >> 5;
    int wm = wid & 1, wn = wid >> 1;   // 2 m-groups x 4 n-groups

    // Staging index math (constant per thread)
    int arow = t >> 2, ac4 = t & 3;    // A: 64 rows x 4 float4 (16 k each)
    int a_wm = arow >> 5, a_mf = (arow >> 4) & 1, a_kkg = ac4 >> 1;
    int a_slot = ((arow >> 3) & 1) + 2 * (ac4 & 1);
    int a_lane0 = (arow & 7) << 2;
    float* a_dsth = &APh[a_wm][a_mf][a_kkg][0];
    float* a_dstl = &APl[a_wm][a_mf][a_kkg][0];

    int wrow = t >> 4, wc4 = t & 15;   // W: 16 k-rows x 16 float4 (64 cols)
    int b_wn = wc4 >> 2, b_nf = (wc4 >> 1) & 1;
    int b_kkg = wrow >> 3, b_slot = (wrow >> 2) & 1;
    int b_lsub = ((wc4 & 1) << 4) | (wrow & 3);   // lane = b_lsub + (i<<2)
    float* b_dsth = &BPh[b_wn][b_nf][b_kkg][0];
    float* b_dstl = &BPl[b_wn][b_nf][b_kkg][0];

    const float* Ag = A + (row0 + arow) * DDv + ac4 * 4;
    const float* Wg = B + wrow * HHv + col0 + wc4 * 4;

    float cacc[2][2][4];
#pragma unroll
    for (int i = 0; i < 2; i++)
#pragma unroll
        for (int j = 0; j < 2; j++)
#pragma unroll
            for (int r = 0; r < 4; r++) cacc[i][j][r] = 0.f;

    // Prefetch chunk 0
    float4 av = *(const float4*)(Ag);
    float4 wv = *(const float4*)(Wg);

    for (int ch = 0; ch < 16; ch++) {
        // Split + stage current chunk in permuted fragment order
        {
            float ah[4] = {tf32r(av.x), tf32r(av.y), tf32r(av.z), tf32r(av.w)};
            float al[4] = {av.x - ah[0], av.y - ah[1], av.z - ah[2], av.w - ah[3]};
            float wh[4] = {tf32r(wv.x), tf32r(wv.y), tf32r(wv.z), tf32r(wv.w)};
            float wl[4] = {wv.x - wh[0], wv.y - wh[1], wv.z - wh[2], wv.w - wh[3]};
#pragma unroll
            for (int i = 0; i < 4; i++) {
                int ai = (a_lane0 + i) * 4 + a_slot;
                a_dsth[ai] = ah[i];
                a_dstl[ai] = al[i];
                int bi = (b_lsub + (i << 2)) * 2 + b_slot;
                b_dsth[bi] = wh[i];
                b_dstl[bi] = wl[i];
            }
        }
        __syncthreads();

        // Issue next chunk's loads NOW — they fly under the MMA/LDS below.
        if (ch + 1 < 16) {
            av = *(const float4*)(Ag + (ch + 1) * 16);
            wv = *(const float4*)(Wg + (ch + 1) * 16 * HHv);
        }

#pragma unroll
        for (int kkg = 0; kkg < 2; kkg++) {
            // Vectorized fragment loads
            float4 fh0 = *(const float4*)&APh[wm][0][kkg][lane * 4];
            float4 fh1 = *(const float4*)&APh[wm][1][kkg][lane * 4];
            float4 fl0 = *(const float4*)&APl[wm][0][kkg][lane * 4];
            float4 fl1 = *(const float4*)&APl[wm][1][kkg][lane * 4];
            float2 bh0 = *(const float2*)&BPh[wn][0][kkg][lane * 2];
            float2 bh1 = *(const float2*)&BPh[wn][1][kkg][lane * 2];
            float2 bl0 = *(const float2*)&BPl[wn][0][kkg][lane * 2];
            float2 bl1 = *(const float2*)&BPl[wn][1][kkg][lane * 2];

            unsigned fah[2][4] = {
                {__float_as_uint(fh0.x), __float_as_uint(fh0.y),
                 __float_as_uint(fh0.z), __float_as_uint(fh0.w)},
                {__float_as_uint(fh1.x), __float_as_uint(fh1.y),
                 __float_as_uint(fh1.z), __float_as_uint(fh1.w)}};
            unsigned fal[2][4] = {
                {__float_as_uint(fl0.x), __float_as_uint(fl0.y),
                 __float_as_uint(fl0.z), __float_as_uint(fl0.w)},
                {__float_as_uint(fl1.x), __float_as_uint(fl1.y),
                 __float_as_uint(fl1.z), __float_as_uint(fl1.w)}};
            unsigned fbh[2][2] = {
                {__float_as_uint(bh0.x), __float_as_uint(bh0.y)},
                {__float_as_uint(bh1.x), __float_as_uint(bh1.y)}};
            unsigned fbl[2][2] = {
                {__float_as_uint(bl0.x), __float_as_uint(bl0.y)},
                {__float_as_uint(bl1.x), __float_as_uint(bl1.y)}};

#pragma unroll
            for (int mf = 0; mf < 2; mf++)
#pragma unroll
                for (int nf = 0; nf < 2; nf++) {
                    mma_tf32(cacc[mf][nf], fah[mf][0], fah[mf][1], fah[mf][2], fah[mf][3],
                             fbh[nf][0], fbh[nf][1]);
                    mma_tf32(cacc[mf][nf], fal[mf][0], fal[mf][1], fal[mf][2], fal[mf][3],
                             fbh[nf][0], fbh[nf][1]);
                    mma_tf32(cacc[mf][nf], fah[mf][0], fah[mf][1], fah[mf][2], fah[mf][3],
                             fbl[nf][0], fbl[nf][1]);
                }
        }
        __syncthreads();
    }

    // Epilogue. C layout per lane: c0=(r,c), c1=(r,c+1), c2=(r+8,c), c3=(r+8,c+1)
#pragma unroll
    for (int mf = 0; mf < 2; mf++)
#pragma unroll
        for (int nf = 0; nf < 2; nf++) {
            int r = row0 + wm * 32 + mf * 16 + (lane >> 2);
            int c = col0 + wn * 16 + nf * 8 + (lane & 3) * 2;
            float* cc = cacc[mf][nf];
            if (!is_k) {
                *(float2*)(g_q + r * HHv + c)       = make_float2(cc[0], cc[1]);
                *(float2*)(g_q + (r + 8) * HHv + c) = make_float2(cc[2], cc[3]);
            } else {
                int bb = r >> 9, m = r & 511;
                unsigned* base = g_kTh + (bb * HHv) * MMv + m;
                base[(c + 0) * MMv]     = packh2(cc[0], cc[0]);
                base[(c + 1) * MMv]     = packh2(cc[1], cc[1]);
                base[(c + 0) * MMv + 8] = packh2(cc[2], cc[2]);
                base[(c + 1) * MMv + 8] = packh2(cc[3], cc[3]);
            }
        }
}

// ---------------------------------------------------------------------------
// Score kernel (R9/R12 body, frozen at MUFU element-rate floor):
// tile (8q x 128m), 128 threads, grid 1024.
// ---------------------------------------------------------------------------
__global__ __launch_bounds__(128) void score_kernel(const float* __restrict__ Wv)
{
    __shared__ __align__(16) uint4 qsh[HHv];
    __shared__ __align__(16) unsigned wsh[HHv];

    int t = threadIdx.x;
    int bid = blockIdx.x;
    int mc = bid & 3;
    int qc = (bid >> 2) & 63;
    int b = bid >> 8;
    int n0 = qc * 8;
    int m = mc * 128 + t;

    {
        const float* qb = g_q + (b * NQv + n0) * HHv + 2 * t;
        float2 r[8];
#pragma unroll
        for (int q = 0; q < 8; q++)
            r[q] = *(const float2*)(qb + q * HHv);
#pragma unroll
        for (int j = 0; j < 2; j++) {
            int h = 2 * t + j;
            float v0 = j ? r[0].y : r[0].x, v1 = j ? r[1].y : r[1].x;
            float v2 = j ? r[2].y : r[2].x, v3 = j ? r[3].y : r[3].x;
            float v4 = j ? r[4].y : r[4].x, v5 = j ? r[5].y : r[5].x;
            float v6 = j ? r[6].y : r[6].x, v7 = j ? r[7].y : r[7].x;
            qsh[h] = make_uint4(packh2(v0, v1), packh2(v2, v3),
                                packh2(v4, v5), packh2(v6, v7));
        }
        float2 wv = *(const float2*)(Wv + 2 * t);
        wsh[2 * t + 0] = packh2(wv.x, wv.x);
        wsh[2 * t + 1] = packh2(wv.y, wv.y);
    }
    __syncthreads();

    float facc[8];
#pragma unroll
    for (int q = 0; q < 8; q++) facc[q] = 0.f;

    const unsigned* kb = g_kTh + (b * HHv) * MMv + m;

    for (int h0 = 0; h0 < HHv; h0 += 8) {
        unsigned acc2[4] = {0u, 0u, 0u, 0u};
#pragma unroll
        for (int hh = 0; hh < 8; hh++) {
            int h = h0 + hh;
            unsigned kk2 = kb[h * MMv];
            uint4 qh = qsh[h];
            unsigned w2 = wsh[h];
            acc2[0] = hfma2(w2, htanh2(hadd2(qh.x, kk2)), acc2[0]);
            acc2[1] = hfma2(w2, htanh2(hadd2(qh.y, kk2)), acc2[1]);
            acc2[2] = hfma2(w2, htanh2(hadd2(qh.z, kk2)), acc2[2]);
            acc2[3] = hfma2(w2, htanh2(hadd2(qh.w, kk2)), acc2[3]);
        }
        drain2(acc2[0], facc[0], facc[1]);
        drain2(acc2[1], facc[2], facc[3]);
        drain2(acc2[2], facc[4], facc[5]);
        drain2(acc2[3], facc[6], facc[7]);
    }

#pragma unroll
    for (int q = 0; q < 8; q++)
        g_sc[(b * NQv + n0 + q) * MMv + m] = facc[q];
}

// ---------------------------------------------------------------------------
// Softmax + AV (R12-proven, frozen): 16q/block + v-split 2, grid 256.
// ---------------------------------------------------------------------------
__global__ __launch_bounds__(256) void softav_kernel(const float* __restrict__ value,
                                                     float* __restrict__ out)
{
    __shared__ __align__(16) float sc[16][MMv];
    __shared__ float inv_s[16];
    float2 (*ps)[16][64] = (float2(*)[16][64])sc;

    int t = threadIdx.x;
    int bid = blockIdx.x;
    int vh = bid & 1;
    int qc = (bid >> 1) & 31;
    int b = bid >> 6;
    int n0 = qc * 16;
    int w = t >> 5, lane = t & 31;

#pragma unroll
    for (int r = 0; r < 2; r++) {
        int row = 2 * w + r;
        const float* srow = g_sc + (b * NQv + n0 + row) * MMv;
        float vals[16];
        float vmax = -1e30f;
#pragma unroll
        for (int j = 0; j < 16; j++) {
            vals[j] = srow[lane + j * 32];
            vmax = fmaxf(vmax, vals[j]);
        }
#pragma unroll
        for (int o = 16; o > 0; o >>= 1)
            vmax = fmaxf(vmax, __shfl_xor_sync(0xffffffffu, vmax, o));
        float sum = 0.f;
#pragma unroll
        for (int j = 0; j < 16; j++) {
            float p = fex2((vals[j] - vmax) * 1.4426950408889634f);
            sc[row][lane + j * 32] = p;
            sum += p;
        }
#pragma unroll
        for (int o = 16; o > 0; o >>= 1)
            sum += __shfl_xor_sync(0xffffffffu, sum, o);
        if (lane == 0) inv_s[row] = 1.0f / sum;
    }
    __syncthreads();

    int mg = t >> 6;
    int vg = t & 63;
    const float* vbase = value + (b * MMv + mg * 128) * DDv + vh * 128 + vg * 2;
    unsigned long long acc[16];
#pragma unroll
    for (int q = 0; q < 16; q++) acc[q] = 0ull;

    for (int m4 = 0; m4 < 128; m4 += 4) {
        float2 v0 = *(const float2*)(vbase + (m4 + 0) * DDv);
        float2 v1 = *(const float2*)(vbase + (m4 + 1) * DDv);
        float2 v2 = *(const float2*)(vbase + (m4 + 2) * DDv);
        float2 v3 = *(const float2*)(vbase + (m4 + 3) * DDv);
        unsigned long long w0 = pk2(v0.x, v0.y);
        unsigned long long w1 = pk2(v1.x, v1.y);
        unsigned long long w2 = pk2(v2.x, v2.y);
        unsigned long long w3 = pk2(v3.x, v3.y);
        int mIdx = mg * 128 + m4;
#pragma unroll
        for (int q = 0; q < 16; q++) {
            float4 p = *(const float4*)&sc[q][mIdx];
            fma2(acc[q], pk2(p.x, p.x), w0);
            fma2(acc[q], pk2(p.y, p.y), w1);
            fma2(acc[q], pk2(p.z, p.z), w2);
            fma2(acc[q], pk2(p.w, p.w), w3);
        }
    }
    __syncthreads();
#pragma unroll
    for (int q = 0; q < 16; q++) ps[mg][q][vg] = up2(acc[q]);
    __syncthreads();

#pragma unroll
    for (int r = 0; r < 4; r++) {
        int p = t + r * 256;
        int q = p >> 6, v2i = p & 63;
        float2 s0 = ps[0][q][v2i];
        float2 s1 = ps[1][q][v2i];
        float2 s2 = ps[2][q][v2i];
        float2 s3 = ps[3][q][v2i];
        float iv = inv_s[q];
        ((float2*)out)[(b * NQv + n0 + q) * 128 + vh * 64 + v2i] =
            make_float2((s0.x + s1.x + s2.x + s3.x) * iv,
                        (s0.y + s1.y + s2.y + s3.y) * iv);
    }
}

extern "C" void kernel_launch(void* const* d_in, const int* in_sizes, int n_in,
                              void* d_out, int out_size)
{
    const float* query = (const float*)d_in[0];
    const float* key   = (const float*)d_in[1];
    const float* value = (const float*)d_in[2];
    const float* Wq    = (const float*)d_in[3];
    const float* Wk    = (const float*)d_in[4];
    const float* Wv    = (const float*)d_in[5];
    float* out = (float*)d_out;

    proj_kernel<<<256, 256>>>(query, key, Wq, Wk);
    score_kernel<<<1024, 128>>>(Wv);
    softav_kernel<<<256, 256>>>(value, out);
}